// round 3
// baseline (speedup 1.0000x reference)
#include <cuda_runtime.h>

#define N_USERS 100000
#define N_ITEMS 50000
#define N_NODES 150000  // N_USERS + N_ITEMS
#define EMBED   64
#define NNZ     4000000
#define BATCH   4096
#define ROW2    32            // EMBED floats = 32 float2
#define ROW4    16            // EMBED floats = 16 float4
#define TOTAL4  (N_NODES * ROW4)

// Padded bucket capacity per node. Degrees ~ Poisson(26.7); max over 150k
// nodes ~52. 128 gives enormous margin and a cheap shift for addressing.
#define CAP     128
#define CAP_LG  7

// ---------------------------------------------------------------------------
// Device-global scratch (static allocation: allowed by harness rules)
// ---------------------------------------------------------------------------
__device__ float g_E0[N_NODES * EMBED];
__device__ float g_E1[N_NODES * EMBED];
__device__ float g_acc[N_NODES * EMBED];

__device__ int   g_cnt[N_NODES];             // degree / scatter cursor
__device__ int2  g_edges[N_NODES * CAP];     // packed (col, a) per bucket slot

// ---------------------------------------------------------------------------
// init: E0 = concat(embed_user, embed_item); acc = E0
// ---------------------------------------------------------------------------
__global__ void lgcn_init(const float4* __restrict__ eu,
                          const float4* __restrict__ ei) {
    float4* E0  = reinterpret_cast<float4*>(g_E0);
    float4* acc = reinterpret_cast<float4*>(g_acc);
    const int stride = gridDim.x * blockDim.x;
    const int user4 = N_USERS * ROW4;
    for (int i = blockIdx.x * blockDim.x + threadIdx.x; i < TOTAL4; i += stride) {
        float4 v = (i < user4) ? eu[i] : ei[i - user4];
        E0[i]  = v;
        acc[i] = v;
    }
}

// ---------------------------------------------------------------------------
// bucket scatter: slot = cnt[r]++ ; edges[r*CAP + slot] = (col, a)
// Single pass; no histogram, no scan.
// ---------------------------------------------------------------------------
__global__ void k_scatter(const int* __restrict__ row,
                          const int* __restrict__ col,
                          const float* __restrict__ a) {
    const int stride = gridDim.x * blockDim.x;
    for (int e = blockIdx.x * blockDim.x + threadIdx.x; e < NNZ; e += stride) {
        const int r = __ldg(row + e);
        int p = atomicAdd(&g_cnt[r], 1);
        int2 pk;
        pk.x = __ldg(col + e);
        pk.y = __float_as_int(__ldg(a + e));
        g_edges[((size_t)r << CAP_LG) + p] = pk;
    }
}

// ---------------------------------------------------------------------------
// Bucket SpMM: one warp per node. Gather-only segment sum, fused acc update.
//   dst[n] = sum_j a[j] * src[col[j]];  acc[n] += dst[n]
// ---------------------------------------------------------------------------
template<bool WRITE_DST>
__global__ void lgcn_csr(const float2* __restrict__ src,
                         float2* __restrict__ dst) {
    const int warp = (blockIdx.x * blockDim.x + threadIdx.x) >> 5;
    const int lane = threadIdx.x & 31;
    if (warp >= N_NODES) return;
    const int2* eb = g_edges + ((size_t)warp << CAP_LG);
    const int   n  = __ldg(&g_cnt[warp]);

    float2 sum = make_float2(0.f, 0.f);
    #pragma unroll 4
    for (int j = 0; j < n; j++) {
        const int2  e  = __ldg(eb + j);          // broadcast (same addr all lanes)
        const float av = __int_as_float(e.y);
        float2 v = __ldg(src + (size_t)e.x * ROW2 + lane);
        sum.x += av * v.x;
        sum.y += av * v.y;
    }
    const size_t o = (size_t)warp * ROW2 + lane;
    if (WRITE_DST) dst[o] = sum;
    float2* acc2 = reinterpret_cast<float2*>(g_acc);
    float2 a0 = acc2[o];
    acc2[o] = make_float2(a0.x + sum.x, a0.y + sum.y);
}

// ---------------------------------------------------------------------------
// gather: out = [acc[user] ; acc[N_USERS+pos] ; acc[N_USERS+neg]] * 0.25
// ---------------------------------------------------------------------------
__global__ void lgcn_gather(const int* __restrict__ bu,
                            const int* __restrict__ bp,
                            const int* __restrict__ bn,
                            float4* __restrict__ out) {
    const float4* acc = reinterpret_cast<const float4*>(g_acc);
    const int tid  = blockIdx.x * blockDim.x + threadIdx.x;
    const int lane = tid & 15;
    const int r    = tid >> 4;
    if (r >= 3 * BATCH) return;
    const int which = r / BATCH;
    const int b     = r - which * BATCH;
    int node;
    if (which == 0)      node = __ldg(bu + b);
    else if (which == 1) node = N_USERS + __ldg(bp + b);
    else                 node = N_USERS + __ldg(bn + b);
    float4 v = acc[(size_t)node * ROW4 + lane];
    const float sc = 0.25f;   // 1/(N_LAYERS+1)
    out[(size_t)r * ROW4 + lane] = make_float4(v.x * sc, v.y * sc, v.z * sc, v.w * sc);
}

// ---------------------------------------------------------------------------
// launch
// ---------------------------------------------------------------------------
extern "C" void kernel_launch(void* const* d_in, const int* in_sizes, int n_in,
                              void* d_out, int out_size) {
    const int*   batch_user = (const int*)  d_in[0];
    const int*   batch_pos  = (const int*)  d_in[1];
    const int*   batch_neg  = (const int*)  d_in[2];
    const float* embed_user = (const float*)d_in[3];
    const float* embed_item = (const float*)d_in[4];
    const int*   row_idx    = (const int*)  d_in[5];
    const int*   col_idx    = (const int*)  d_in[6];
    const float* a_vals     = (const float*)d_in[7];
    float* out = (float*)d_out;

    float2* E0 = nullptr;
    float2* E1 = nullptr;
    void*   cntp = nullptr;
    cudaGetSymbolAddress((void**)&E0, g_E0);
    cudaGetSymbolAddress((void**)&E1, g_E1);
    cudaGetSymbolAddress(&cntp, g_cnt);

    const int T = 256;
    const int initBlocks   = 2048;
    const int edgeBlocks   = 148 * 8;
    const int csrBlocks    = (N_NODES * 32 + T - 1) / T;          // warp/node
    const int gatherBlocks = (3 * BATCH * 16 + T - 1) / T;

    // zero cursors, init embeddings, single-pass bucket scatter
    cudaMemsetAsync(cntp, 0, N_NODES * sizeof(int));
    lgcn_init<<<initBlocks, T>>>((const float4*)embed_user,
                                 (const float4*)embed_item);
    k_scatter<<<edgeBlocks, T>>>(row_idx, col_idx, a_vals);

    // 3 propagation layers, acc fused
    lgcn_csr<true ><<<csrBlocks, T>>>(E0, E1);   // layer 1: E0 -> E1
    lgcn_csr<true ><<<csrBlocks, T>>>(E1, E0);   // layer 2: E1 -> E0
    lgcn_csr<false><<<csrBlocks, T>>>(E0, E1);   // layer 3: acc only

    lgcn_gather<<<gatherBlocks, T>>>(batch_user, batch_pos, batch_neg,
                                     (float4*)out);
}

// round 4
// speedup vs baseline: 1.2598x; 1.2598x over previous
#include <cuda_runtime.h>
#include <cuda_fp16.h>

#define N_USERS 100000
#define N_ITEMS 50000
#define N_NODES 150000  // N_USERS + N_ITEMS
#define EMBED   64
#define NNZ     4000000
#define BATCH   4096
#define ROW2    32            // EMBED floats  = 32 float2 ; also 32 half2
#define ROW4    16            // EMBED floats  = 16 float4
#define TOTAL2  (N_NODES * ROW2)

// ---------------------------------------------------------------------------
// Device-global scratch (static allocation: allowed by harness rules)
// E0h/E1h: propagated embeddings in fp16 (one 128B line per node row).
// acc: running sum in fp32 (precision-critical).
// ---------------------------------------------------------------------------
__device__ __half g_E0h[N_NODES * EMBED];
__device__ __half g_E1h[N_NODES * EMBED];
__device__ float  g_acc[N_NODES * EMBED];

__device__ int  g_cnt[N_NODES];    // degree histogram
__device__ int  g_off[N_NODES];    // exclusive offsets
__device__ int  g_cur[N_NODES];    // scatter cursors
__device__ int  g_bsum[256];       // block sums for scan (147 used)
__device__ int2 g_edges[NNZ];      // packed (col, a) sorted by row — 32 MB dense

// ---------------------------------------------------------------------------
// init: acc = concat(embed_user, embed_item); E0h = fp16(acc)
// ---------------------------------------------------------------------------
__global__ void lgcn_init(const float2* __restrict__ eu,
                          const float2* __restrict__ ei) {
    float2* acc2 = reinterpret_cast<float2*>(g_acc);
    half2*  E0h2 = reinterpret_cast<half2*>(g_E0h);
    const int stride = gridDim.x * blockDim.x;
    const int user2 = N_USERS * ROW2;
    for (int i = blockIdx.x * blockDim.x + threadIdx.x; i < TOTAL2; i += stride) {
        float2 v = (i < user2) ? eu[i] : ei[i - user2];
        acc2[i] = v;
        E0h2[i] = __float22half2_rn(v);
    }
}

// ---------------------------------------------------------------------------
// CSR build: histogram -> 2-level exclusive scan -> scatter (counting sort)
// ---------------------------------------------------------------------------
__global__ void k_hist(const int* __restrict__ row) {
    const int stride = gridDim.x * blockDim.x;
    for (int e = blockIdx.x * blockDim.x + threadIdx.x; e < NNZ; e += stride)
        atomicAdd(&g_cnt[__ldg(row + e)], 1);   // no return -> RED
}

#define SCAN_B 1024
__global__ void k_scan_local() {
    __shared__ int s[SCAN_B];
    const int tid = threadIdx.x;
    const int i = blockIdx.x * SCAN_B + tid;
    int v = (i < N_NODES) ? g_cnt[i] : 0;
    s[tid] = v;
    __syncthreads();
    #pragma unroll
    for (int d = 1; d < SCAN_B; d <<= 1) {
        int t = (tid >= d) ? s[tid - d] : 0;
        __syncthreads();
        s[tid] += t;
        __syncthreads();
    }
    if (i < N_NODES) g_off[i] = s[tid] - v;          // exclusive
    if (tid == SCAN_B - 1) g_bsum[blockIdx.x] = s[tid];
}

__global__ void k_scan_bsum(int nblocks) {
    __shared__ int s[256];
    const int tid = threadIdx.x;
    int v = (tid < nblocks) ? g_bsum[tid] : 0;
    s[tid] = v;
    __syncthreads();
    #pragma unroll
    for (int d = 1; d < 256; d <<= 1) {
        int t = (tid >= d) ? s[tid - d] : 0;
        __syncthreads();
        s[tid] += t;
        __syncthreads();
    }
    if (tid < nblocks) g_bsum[tid] = s[tid] - v;     // exclusive
}

__global__ void k_scan_add() {
    const int i = blockIdx.x * blockDim.x + threadIdx.x;
    if (i >= N_NODES) return;
    int o = g_off[i] + g_bsum[i / SCAN_B];
    g_off[i] = o;
    g_cur[i] = o;
}

__global__ void k_scatter(const int* __restrict__ row,
                          const int* __restrict__ col,
                          const float* __restrict__ a) {
    const int stride = gridDim.x * blockDim.x;
    for (int e = blockIdx.x * blockDim.x + threadIdx.x; e < NNZ; e += stride) {
        const int r = __ldg(row + e);
        int p = atomicAdd(&g_cur[r], 1);
        int2 pk;
        pk.x = __ldg(col + e);
        pk.y = __float_as_int(__ldg(a + e));
        g_edges[p] = pk;
    }
}

// ---------------------------------------------------------------------------
// CSR SpMM, fp16 src/dst, fp32 accumulate. One warp per node; lane = half2.
//   dst[n] = fp16( sum_j a[j] * src[col[j]] );  acc[n] += sum  (fp32)
// ---------------------------------------------------------------------------
template<bool WRITE_DST>
__global__ void lgcn_csr(const half2* __restrict__ src,
                         half2* __restrict__ dst) {
    const int warp = (blockIdx.x * blockDim.x + threadIdx.x) >> 5;
    const int lane = threadIdx.x & 31;
    if (warp >= N_NODES) return;
    const int s = __ldg(&g_off[warp]);
    const int n = __ldg(&g_cnt[warp]);

    float2 sum = make_float2(0.f, 0.f);
    #pragma unroll 4
    for (int j = 0; j < n; j++) {
        const int2  e  = __ldg(g_edges + s + j);     // broadcast load
        const float av = __int_as_float(e.y);
        half2  h = __ldg(src + (size_t)e.x * ROW2 + lane);
        float2 v = __half22float2(h);
        sum.x += av * v.x;
        sum.y += av * v.y;
    }
    const size_t o = (size_t)warp * ROW2 + lane;
    if (WRITE_DST) dst[o] = __float22half2_rn(sum);
    float2* acc2 = reinterpret_cast<float2*>(g_acc);
    float2 a0 = acc2[o];
    acc2[o] = make_float2(a0.x + sum.x, a0.y + sum.y);
}

// ---------------------------------------------------------------------------
// gather: out = [acc[user] ; acc[N_USERS+pos] ; acc[N_USERS+neg]] * 0.25
// ---------------------------------------------------------------------------
__global__ void lgcn_gather(const int* __restrict__ bu,
                            const int* __restrict__ bp,
                            const int* __restrict__ bn,
                            float4* __restrict__ out) {
    const float4* acc = reinterpret_cast<const float4*>(g_acc);
    const int tid  = blockIdx.x * blockDim.x + threadIdx.x;
    const int lane = tid & 15;
    const int r    = tid >> 4;
    if (r >= 3 * BATCH) return;
    const int which = r / BATCH;
    const int b     = r - which * BATCH;
    int node;
    if (which == 0)      node = __ldg(bu + b);
    else if (which == 1) node = N_USERS + __ldg(bp + b);
    else                 node = N_USERS + __ldg(bn + b);
    float4 v = acc[(size_t)node * ROW4 + lane];
    const float sc = 0.25f;   // 1/(N_LAYERS+1)
    out[(size_t)r * ROW4 + lane] = make_float4(v.x * sc, v.y * sc, v.z * sc, v.w * sc);
}

// ---------------------------------------------------------------------------
// launch
// ---------------------------------------------------------------------------
extern "C" void kernel_launch(void* const* d_in, const int* in_sizes, int n_in,
                              void* d_out, int out_size) {
    const int*   batch_user = (const int*)  d_in[0];
    const int*   batch_pos  = (const int*)  d_in[1];
    const int*   batch_neg  = (const int*)  d_in[2];
    const float* embed_user = (const float*)d_in[3];
    const float* embed_item = (const float*)d_in[4];
    const int*   row_idx    = (const int*)  d_in[5];
    const int*   col_idx    = (const int*)  d_in[6];
    const float* a_vals     = (const float*)d_in[7];
    float* out = (float*)d_out;

    half2* E0 = nullptr;
    half2* E1 = nullptr;
    void*  cntp = nullptr;
    cudaGetSymbolAddress((void**)&E0, g_E0h);
    cudaGetSymbolAddress((void**)&E1, g_E1h);
    cudaGetSymbolAddress(&cntp, g_cnt);

    const int T = 256;
    const int initBlocks   = 2048;
    const int edgeBlocks   = 148 * 8;
    const int scanBlocks   = (N_NODES + SCAN_B - 1) / SCAN_B;     // 147
    const int addBlocks    = (N_NODES + T - 1) / T;
    const int csrBlocks    = (N_NODES * 32 + T - 1) / T;          // warp/node
    const int gatherBlocks = (3 * BATCH * 16 + T - 1) / T;

    cudaMemsetAsync(cntp, 0, N_NODES * sizeof(int));
    lgcn_init<<<initBlocks, T>>>((const float2*)embed_user,
                                 (const float2*)embed_item);

    // build compact CSR (counting sort by row)
    k_hist<<<edgeBlocks, T>>>(row_idx);
    k_scan_local<<<scanBlocks, SCAN_B>>>();
    k_scan_bsum<<<1, 256>>>(scanBlocks);
    k_scan_add<<<addBlocks, T>>>();
    k_scatter<<<edgeBlocks, T>>>(row_idx, col_idx, a_vals);

    // 3 propagation layers, acc fused
    lgcn_csr<true ><<<csrBlocks, T>>>(E0, E1);   // layer 1: E0 -> E1
    lgcn_csr<true ><<<csrBlocks, T>>>(E1, E0);   // layer 2: E1 -> E0
    lgcn_csr<false><<<csrBlocks, T>>>(E0, E1);   // layer 3: acc only

    lgcn_gather<<<gatherBlocks, T>>>(batch_user, batch_pos, batch_neg,
                                     (float4*)out);
}